// round 13
// baseline (speedup 1.0000x reference)
#include <cuda_runtime.h>
#include <cuda_fp16.h>
#include <cstddef>
#include <cstdint>

#define NN   50000
#define RR   3
#define EE   800000
#define HIDD 128
#define KK   (RR * HIDD)            // 384
#define SB   256
#define NBLK ((NN + SB - 1) / SB)   // 196
#define GRIDB (NBLK * RR)           // 588 blocks for build_csr

// ---------------- static scratch (no cudaMalloc allowed) ----------------
__device__ int    g_outdeg[RR * NN];
__device__ int    g_indeg [RR * NN];
__device__ float  g_rout  [RR * NN];
__device__ float  g_rin   [RR * NN];
__device__ int    g_rowptr[RR * (NN + 1)];
__device__ int    g_cursor[RR * (NN + 1)];
__device__ int    g_bsum  [RR][NBLK];
__device__ int2   g_edge  [RR * EE];                  // (src col, weight bits)
__device__ __half g_zh    [(size_t)NN * KK];          // SpMM output (GEMM A), fp16
__device__ __half g_hh    [2][(size_t)NN * HIDD];     // layer activations, fp16
__device__ __half g_xh    [(size_t)NN * HIDD];        // fp16 copy of x
__device__ __half g_wt    [4][HIDD][KK];              // transposed fp16 weights [n][k]
__device__ __half g_wcmb  [64][KK];                   // combined (W4 @ Wout / 3)^T fp16
__device__ float  g_bcmb  [64];                       // combined bias for final output
__device__ unsigned g_barrier;                        // monotonic grid barrier counter

// ---------------- prep: x->fp16 + weight transpose/convert + Wcomb ----------------
__global__ void prep_kernel(const float* __restrict__ x,
                            const float* __restrict__ W0,
                            const float* __restrict__ Wl,
                            const float* __restrict__ bl,
                            const float* __restrict__ Wout,
                            const float* __restrict__ bout) {
    int i = blockIdx.x * blockDim.x + threadIdx.x;
    if (i < NN * HIDD / 2) {
        float2 v = ((const float2*)x)[i];
        ((__half2*)g_xh)[i] = __floats2half2_rn(v.x, v.y);
    }
    if (i < 4 * HIDD * KK) {
        int L = i / (HIDD * KK);
        int rem = i - L * (HIDD * KK);
        int n = rem / KK;
        int k = rem - n * KK;
        const float* src = (L == 0) ? W0 : (Wl + (size_t)(L - 1) * KK * HIDD);
        g_wt[L][n][k] = __float2half_rn(src[(size_t)k * HIDD + n]);
    }
    if (i < 64 * KK) {
        int n = i / KK;
        int k = i - n * KK;
        const float* W4 = Wl + (size_t)3 * KK * HIDD;   // [384][128]
        float s = 0.f;
        #pragma unroll 4
        for (int j = 0; j < HIDD; j++)
            s = fmaf(W4[(size_t)k * HIDD + j], Wout[(size_t)j * 64 + n], s);
        g_wcmb[n][k] = __float2half_rn(s * (1.0f / 3.0f));
    }
    if (i < 64) {
        const float* b4 = bl + (size_t)3 * RR * HIDD;
        float s = 0.f;
        for (int j = 0; j < HIDD; j++) {
            float bj = (b4[j] + b4[HIDD + j] + b4[2 * HIDD + j]) * (1.0f / 3.0f);
            s = fmaf(bj, Wout[(size_t)j * 64 + i], s);
        }
        g_bcmb[i] = s + bout[i];
    }
}

// ---------------- software grid barrier (monotonic, replay-safe) ----------------
__device__ __forceinline__ void grid_sync_sw() {
    __syncthreads();
    if (threadIdx.x == 0) {
        __threadfence();
        unsigned ticket = atomicAdd(&g_barrier, 1u);
        unsigned target = (ticket / GRIDB + 1u) * GRIDB;
        while ((int)(*(volatile unsigned*)&g_barrier - target) < 0) __nanosleep(40);
        __threadfence();
    }
    __syncthreads();
}

__device__ __forceinline__ int warp_incl_scan(int v, int lane) {
    #pragma unroll
    for (int o = 1; o < 32; o <<= 1) {
        int t = __shfl_up_sync(0xFFFFFFFFu, v, o);
        if (lane >= o) v += t;
    }
    return v;
}

// ---------------- full CSR build in one launch (588 blocks, 4 grid syncs) ----------------
__global__ __launch_bounds__(SB)
void build_csr_kernel(const int* __restrict__ src, const int* __restrict__ dst) {
    const int gthreads = GRIDB * SB;
    int b = blockIdx.x, tid = threadIdx.x;
    int gtid = b * SB + tid;
    int lane = tid & 31, wid = tid >> 5;

    // phase 0: zero degree arrays
    for (int i = gtid; i < RR * NN; i += gthreads) { g_outdeg[i] = 0; g_indeg[i] = 0; }
    grid_sync_sw();

    // phase 1: degree histograms
    for (int i = gtid; i < RR * EE; i += gthreads) {
        int r = i / EE;
        atomicAdd(&g_outdeg[r * NN + src[i]], 1);
        atomicAdd(&g_indeg [r * NN + dst[i]], 1);
    }
    grid_sync_sw();

    int r = b / NBLK, blk = b - r * NBLK;
    __shared__ int ws[8];
    __shared__ int s_boff;

    // phase 2: norms + per-block degree sums
    {
        int i = blk * SB + tid;
        int v = 0;
        if (i < NN) {
            int od = g_outdeg[r * NN + i];
            int id = g_indeg [r * NN + i];
            g_rout[r * NN + i] = rsqrtf(fmaxf((float)od, 1.0f));
            g_rin [r * NN + i] = rsqrtf(fmaxf((float)id, 1.0f));
            v = id;
        }
        int s = v;
        #pragma unroll
        for (int o = 16; o > 0; o >>= 1) s += __shfl_down_sync(0xFFFFFFFFu, s, o);
        if (lane == 0) ws[wid] = s;
        __syncthreads();
        if (tid == 0) {
            int t = 0;
            #pragma unroll
            for (int w = 0; w < 8; w++) t += ws[w];
            g_bsum[r][blk] = t;
        }
    }
    grid_sync_sw();

    // phase 3: rowptr = block-offset + local exclusive scan
    {
        if (wid == 0) {
            int s = 0;
            for (int i = lane; i < blk; i += 32) s += g_bsum[r][i];
            #pragma unroll
            for (int o = 16; o > 0; o >>= 1) s += __shfl_down_sync(0xFFFFFFFFu, s, o);
            if (lane == 0) s_boff = s;
        }
        __syncthreads();
        int i = blk * SB + tid;
        int v = (i < NN) ? g_indeg[r * NN + i] : 0;
        int incl = warp_incl_scan(v, lane);
        if (lane == 31) ws[wid] = incl;
        __syncthreads();
        if (wid == 0) {
            int t = (lane < 8) ? ws[lane] : 0;
            t = warp_incl_scan(t, lane);
            if (lane < 8) ws[lane] = t;
        }
        __syncthreads();
        incl += (wid > 0) ? ws[wid - 1] : 0;
        int excl = s_boff + incl - v;
        if (i < NN) {
            g_rowptr[r * (NN + 1) + i] = excl;
            g_cursor[r * (NN + 1) + i] = excl;
        }
        if (blk == NBLK - 1 && tid == SB - 1)
            g_rowptr[r * (NN + 1) + NN] = s_boff + incl;
    }
    grid_sync_sw();

    // phase 4: fill edge records
    for (int i = gtid; i < RR * EE; i += gthreads) {
        int rr = i / EE;
        int d = dst[i];
        int s = src[i];
        int pos = atomicAdd(&g_cursor[rr * (NN + 1) + d], 1);
        g_edge[(size_t)rr * EE + pos] = make_int2(s, __float_as_int(g_rout[rr * NN + s]));
    }
}

// ---------------- SpMM: one warp per (relation, dst-row), MLP-8 fp16 gather ----------------
__global__ void spmm_kernel(int in_sel) {
    int gw   = (blockIdx.x * blockDim.x + threadIdx.x) >> 5;
    int lane = threadIdx.x & 31;
    if (gw >= RR * NN) return;
    int r = gw / NN;
    int n = gw - r * NN;

    const __half* hin = (in_sel < 0) ? g_xh : g_hh[in_sel];
    const uint2* h2 = (const uint2*)hin;
    const int2* edges = g_edge + (size_t)r * EE;

    int start = g_rowptr[r * (NN + 1) + n];
    int end   = g_rowptr[r * (NN + 1) + n + 1];

    float4 acc = make_float4(0.f, 0.f, 0.f, 0.f);
    int e = start;
    #pragma unroll 1
    for (; e + 8 <= end; e += 8) {
        int2 ed[8];
        #pragma unroll
        for (int j = 0; j < 8; j++) ed[j] = edges[e + j];
        uint2 u[8];
        #pragma unroll
        for (int j = 0; j < 8; j++) u[j] = h2[(size_t)ed[j].x * 32 + lane];
        #pragma unroll
        for (int j = 0; j < 8; j++) {
            float w = __int_as_float(ed[j].y);
            float2 a = __half22float2(*(__half2*)&u[j].x);
            float2 b = __half22float2(*(__half2*)&u[j].y);
            acc.x = fmaf(w, a.x, acc.x); acc.y = fmaf(w, a.y, acc.y);
            acc.z = fmaf(w, b.x, acc.z); acc.w = fmaf(w, b.y, acc.w);
        }
    }
    if (e + 4 <= end) {
        int2 ed[4];
        #pragma unroll
        for (int j = 0; j < 4; j++) ed[j] = edges[e + j];
        uint2 u[4];
        #pragma unroll
        for (int j = 0; j < 4; j++) u[j] = h2[(size_t)ed[j].x * 32 + lane];
        #pragma unroll
        for (int j = 0; j < 4; j++) {
            float w = __int_as_float(ed[j].y);
            float2 a = __half22float2(*(__half2*)&u[j].x);
            float2 b = __half22float2(*(__half2*)&u[j].y);
            acc.x = fmaf(w, a.x, acc.x); acc.y = fmaf(w, a.y, acc.y);
            acc.z = fmaf(w, b.x, acc.z); acc.w = fmaf(w, b.y, acc.w);
        }
        e += 4;
    }
    for (; e < end; e++) {
        int2 ed = edges[e];
        float w = __int_as_float(ed.y);
        uint2 u = h2[(size_t)ed.x * 32 + lane];
        float2 a = __half22float2(*(__half2*)&u.x), b = __half22float2(*(__half2*)&u.y);
        acc.x = fmaf(w, a.x, acc.x); acc.y = fmaf(w, a.y, acc.y);
        acc.z = fmaf(w, b.x, acc.z); acc.w = fmaf(w, b.y, acc.w);
    }
    float ri = g_rin[r * NN + n];
    uint2 o;
    *(__half2*)&o.x = __floats2half2_rn(acc.x * ri, acc.y * ri);
    *(__half2*)&o.y = __floats2half2_rn(acc.z * ri, acc.w * ri);
    ((uint2*)g_zh)[((size_t)n * RR + r) * 32 + lane] = o;
}

// ---------------- fp16 tensor-core GEMM: cp.async double-buffered ----------------
__device__ __forceinline__ void mma_f16(float* c, const uint32_t* a,
                                        uint32_t b0, uint32_t b1) {
    asm volatile(
        "mma.sync.aligned.m16n8k16.row.col.f32.f16.f16.f32 "
        "{%0,%1,%2,%3}, {%4,%5,%6,%7}, {%8,%9}, {%0,%1,%2,%3};"
        : "+f"(c[0]), "+f"(c[1]), "+f"(c[2]), "+f"(c[3])
        : "r"(a[0]), "r"(a[1]), "r"(a[2]), "r"(a[3]), "r"(b0), "r"(b1));
}

__device__ __forceinline__ void ldsm_x4(uint32_t* d, uint32_t addr) {
    asm volatile("ldmatrix.sync.aligned.m8n8.x4.shared.b16 {%0,%1,%2,%3}, [%4];"
                 : "=r"(d[0]), "=r"(d[1]), "=r"(d[2]), "=r"(d[3]) : "r"(addr));
}

__device__ __forceinline__ void ldsm_x2(uint32_t& d0, uint32_t& d1, uint32_t addr) {
    asm volatile("ldmatrix.sync.aligned.m8n8.x2.shared.b16 {%0,%1}, [%2];"
                 : "=r"(d0), "=r"(d1) : "r"(addr));
}

__device__ __forceinline__ void cp_async16(void* smem_dst, const void* gsrc) {
    uint32_t d = (uint32_t)__cvta_generic_to_shared(smem_dst);
    asm volatile("cp.async.cg.shared.global [%0], [%1], 16;" :: "r"(d), "l"(gsrc));
}

// C[M,BN] = (A[M,K] @ Wt^T + bias) * alpha.
// wsel: 0..3 -> g_wt[wsel], 4 -> g_wcmb.  bias_sel: -1 -> g_bcmb else passed ptr.
// o_sel: 0/1 -> g_hh[o_sel] (fp16), 2 -> Cext (fp32).
template <int BN, int WN, int NT>
__global__ __launch_bounds__(NT)
void gemm_tc_kernel(int wsel,
                    const float* __restrict__ bias, int biasRows, int bias_sel,
                    int o_sel, float* __restrict__ Cext,
                    float alpha, int leaky) {
    const int BM = 128, BK = 64, PAD = 8, LDW = BK + PAD;   // 72 halves
    const int K = KK, NK = K / BK;                           // 6
    const __half* A  = g_zh;
    const __half* Wt = (wsel < 4) ? &g_wt[wsel][0][0] : &g_wcmb[0][0];
    __half* Hout = (o_sel == 2) ? nullptr : g_hh[o_sel];
    const float* bptr = (bias_sel < 0) ? g_bcmb : bias;

    extern __shared__ __half smh[];
    __half* AsB = smh;                       // 2 stages of [BM][LDW]
    __half* BsB = smh + 2 * BM * LDW;        // 2 stages of [BN][LDW]

    int tid  = threadIdx.x;
    int wid  = tid >> 5;
    int lane = tid & 31;
    int g    = lane >> 2;
    int tg   = lane & 3;
    int wm   = wid / WN;
    int wn   = wid % WN;
    int blockRow = blockIdx.x * BM;

    uint32_t as0 = (uint32_t)__cvta_generic_to_shared(AsB);
    uint32_t bs0 = (uint32_t)__cvta_generic_to_shared(BsB);

    int a_row = wm * 64 + (lane & 15);
    int a_col = (lane >> 4) * 8;
    int b_row = wn * 32 + (lane & 7);
    int b_col = ((lane >> 3) & 1) * 8;

    float acc[4][4][4];
    #pragma unroll
    for (int i = 0; i < 4; i++)
        #pragma unroll
        for (int j = 0; j < 4; j++)
            #pragma unroll
            for (int q = 0; q < 4; q++) acc[i][j][q] = 0.f;

    const int ASLOT = BM * (BK / 8);
    const int BSLOT = BN * (BK / 8);

    auto issue_load = [&](int st, int k0) {
        __half* As = AsB + st * BM * LDW;
        __half* Bs = BsB + st * BN * LDW;
        #pragma unroll
        for (int i = 0; i < ASLOT / NT; i++) {
            int v = tid + i * NT;
            int row = v >> 3, kq = v & 7;
            int gr = blockRow + row;
            void* dstp = &As[row * LDW + kq * 8];
            if (gr < NN) cp_async16(dstp, A + (size_t)gr * K + k0 + kq * 8);
            else         *(uint4*)dstp = make_uint4(0, 0, 0, 0);
        }
        #pragma unroll
        for (int i = 0; i < BSLOT / NT; i++) {
            int v = tid + i * NT;
            int n = v >> 3, kq = v & 7;
            cp_async16(&Bs[n * LDW + kq * 8], Wt + (size_t)n * K + k0 + kq * 8);
        }
    };

    issue_load(0, 0);
    asm volatile("cp.async.commit_group;");

    for (int kt = 0; kt < NK; kt++) {
        if (kt + 1 < NK) {
            issue_load((kt + 1) & 1, (kt + 1) * BK);
            asm volatile("cp.async.commit_group;");
            asm volatile("cp.async.wait_group 1;");
        } else {
            asm volatile("cp.async.wait_group 0;");
        }
        __syncthreads();

        int st = kt & 1;
        uint32_t as_base = as0 + (uint32_t)(st * BM * LDW * 2);
        uint32_t bs_base = bs0 + (uint32_t)(st * BN * LDW * 2);

        #pragma unroll
        for (int kk = 0; kk < BK / 16; kk++) {
            int kb = kk * 16;
            uint32_t af[4][4];
            #pragma unroll
            for (int mt = 0; mt < 4; mt++) {
                uint32_t addr = as_base +
                    (uint32_t)(((a_row + mt * 16) * LDW + kb + a_col) * 2);
                ldsm_x4(af[mt], addr);
            }
            #pragma unroll
            for (int nt = 0; nt < 4; nt++) {
                uint32_t b0, b1;
                uint32_t addr = bs_base +
                    (uint32_t)(((b_row + nt * 8) * LDW + kb + b_col) * 2);
                ldsm_x2(b0, b1, addr);
                #pragma unroll
                for (int mt = 0; mt < 4; mt++)
                    mma_f16(acc[mt][nt], af[mt], b0, b1);
            }
        }
        __syncthreads();
    }

    // ---- epilogue ----
    float2 bs[4];
    #pragma unroll
    for (int nt = 0; nt < 4; nt++) {
        int col = wn * 32 + nt * 8 + tg * 2;
        float sx = 0.f, sy = 0.f;
        for (int rr = 0; rr < biasRows; rr++) {
            sx += bptr[rr * BN + col];
            sy += bptr[rr * BN + col + 1];
        }
        bs[nt].x = sx; bs[nt].y = sy;
    }
    #pragma unroll
    for (int mt = 0; mt < 4; mt++) {
        int r0 = blockRow + wm * 64 + mt * 16 + g;
        int r1 = r0 + 8;
        #pragma unroll
        for (int nt = 0; nt < 4; nt++) {
            int col = wn * 32 + nt * 8 + tg * 2;
            float v0 = (acc[mt][nt][0] + bs[nt].x) * alpha;
            float v1 = (acc[mt][nt][1] + bs[nt].y) * alpha;
            float v2 = (acc[mt][nt][2] + bs[nt].x) * alpha;
            float v3 = (acc[mt][nt][3] + bs[nt].y) * alpha;
            if (leaky) {
                if (v0 < 0.f) v0 *= 0.01f;
                if (v1 < 0.f) v1 *= 0.01f;
                if (v2 < 0.f) v2 *= 0.01f;
                if (v3 < 0.f) v3 *= 0.01f;
            }
            if (o_sel == 2) {
                if (r0 < NN) *(float2*)(Cext + (size_t)r0 * BN + col) = make_float2(v0, v1);
                if (r1 < NN) *(float2*)(Cext + (size_t)r1 * BN + col) = make_float2(v2, v3);
            } else {
                if (r0 < NN) *(__half2*)(Hout + (size_t)r0 * HIDD + col) = __floats2half2_rn(v0, v1);
                if (r1 < NN) *(__half2*)(Hout + (size_t)r1 * HIDD + col) = __floats2half2_rn(v2, v3);
            }
        }
    }
}

// ---------------- launcher ----------------
extern "C" void kernel_launch(void* const* d_in, const int* in_sizes, int n_in,
                              void* d_out, int out_size) {
    const float* x    = (const float*)d_in[0];
    const int*   esrc = (const int*)  d_in[1];
    const int*   edst = (const int*)  d_in[2];
    const float* W0   = (const float*)d_in[3];
    const float* b0   = (const float*)d_in[4];
    const float* Wl   = (const float*)d_in[5];
    const float* bl   = (const float*)d_in[6];
    const float* Wout = (const float*)d_in[7];
    const float* bout = (const float*)d_in[8];
    float* out = (float*)d_out;

    const int SM128 = (2 * 128 * 72 + 2 * 128 * 72) * 2;   // 73728 B
    const int SM64  = (2 * 128 * 72 + 2 * 64 * 72) * 2;    // 55296 B
    cudaFuncSetAttribute((const void*)gemm_tc_kernel<128, 4, 256>,
                         cudaFuncAttributeMaxDynamicSharedMemorySize, SM128);
    cudaFuncSetAttribute((const void*)gemm_tc_kernel<64, 2, 128>,
                         cudaFuncAttributeMaxDynamicSharedMemorySize, SM64);

    // launch 0: prep, 1: CSR build, 2: spmm, 3: gemm (ncu window target)
    prep_kernel<<<(NN * HIDD / 2 + 255) / 256, 256>>>(x, W0, Wl, bl, Wout, bout);
    build_csr_kernel<<<GRIDB, SB>>>(esrc, edst);

    const int spmm_blocks = (RR * NN * 32 + 255) / 256;
    const int gemm_blocks = (NN + 127) / 128;   // 391
    const float inv_r = 1.0f / (float)RR;

    spmm_kernel<<<spmm_blocks, 256>>>(-1);
    gemm_tc_kernel<128, 4, 256><<<gemm_blocks, 256, SM128>>>(
        0, b0, RR, 0, 0, nullptr, inv_r, 1);
    for (int l = 0; l < 3; l++) {
        spmm_kernel<<<spmm_blocks, 256>>>(l & 1 ? 1 : 0);
        gemm_tc_kernel<128, 4, 256><<<gemm_blocks, 256, SM128>>>(
            l + 1, bl + (size_t)l * RR * HIDD, RR, 0,
            (l & 1) ? 0 : 1, nullptr, inv_r, 1);
    }
    // conv layer 4 + final linear folded
    spmm_kernel<<<spmm_blocks, 256>>>(1);
    gemm_tc_kernel<64, 2, 128><<<gemm_blocks, 128, SM64>>>(
        4, nullptr, 1, -1, 2, out, 1.0f, 0);
}

// round 14
// speedup vs baseline: 1.4731x; 1.4731x over previous
#include <cuda_runtime.h>
#include <cuda_fp16.h>
#include <cstddef>
#include <cstdint>

#define NN   50000
#define RR   3
#define EE   800000
#define HIDD 128
#define KK   (RR * HIDD)            // 384
#define SB   256
#define NBLK ((NN + SB - 1) / SB)   // 196
#define GRIDB (NBLK * RR)           // 588

#define FLAG_A (1u << 30)
#define FLAG_P (1u << 31)
#define VALMASK ((1u << 30) - 1u)

// ---------------- static scratch (no cudaMalloc allowed) ----------------
__device__ int      g_outdeg[RR * NN];
__device__ int      g_indeg [RR * NN];
__device__ float    g_rout  [RR * NN];
__device__ float    g_rin   [RR * NN];
__device__ int      g_rowptr[RR * (NN + 1)];
__device__ int      g_cursor[RR * (NN + 1)];
__device__ unsigned g_state [GRIDB];                  // lookback scan states
__device__ int2     g_edge  [RR * EE];                // (src col, weight bits)
__device__ __half   g_zh    [(size_t)NN * KK];        // SpMM output (GEMM A), fp16
__device__ __half   g_hh    [2][(size_t)NN * HIDD];   // layer activations, fp16
__device__ __half   g_xh    [(size_t)NN * HIDD];      // fp16 copy of x
__device__ __half   g_wt    [4][HIDD][KK];            // transposed fp16 weights [n][k]
__device__ __half   g_wcmb  [64][KK];                 // combined (W4 @ Wout / 3)^T fp16
__device__ float    g_bcmb  [64];                     // combined bias for final output

// ---------------- launch 0: prep (x->fp16, weights) + degree histogram ----------------
__global__ void predeg_kernel(const float* __restrict__ x,
                              const int* __restrict__ src,
                              const int* __restrict__ dst,
                              const float* __restrict__ W0,
                              const float* __restrict__ Wl,
                              const float* __restrict__ bl,
                              const float* __restrict__ Wout,
                              const float* __restrict__ bout) {
    int i = blockIdx.x * blockDim.x + threadIdx.x;
    if (i < NN * HIDD / 2) {
        float2 v = ((const float2*)x)[i];
        ((__half2*)g_xh)[i] = __floats2half2_rn(v.x, v.y);
    }
    if (i < RR * EE) {
        int r = i / EE;
        atomicAdd(&g_outdeg[r * NN + src[i]], 1);
        atomicAdd(&g_indeg [r * NN + dst[i]], 1);
    }
    if (i < 4 * HIDD * KK) {
        int L = i / (HIDD * KK);
        int rem = i - L * (HIDD * KK);
        int n = rem / KK;
        int k = rem - n * KK;
        const float* srcw = (L == 0) ? W0 : (Wl + (size_t)(L - 1) * KK * HIDD);
        g_wt[L][n][k] = __float2half_rn(srcw[(size_t)k * HIDD + n]);
    }
    if (i < 64 * KK) {
        int n = i / KK;
        int k = i - n * KK;
        const float* W4 = Wl + (size_t)3 * KK * HIDD;   // [384][128]
        float s = 0.f;
        #pragma unroll 4
        for (int j = 0; j < HIDD; j++)
            s = fmaf(W4[(size_t)k * HIDD + j], Wout[(size_t)j * 64 + n], s);
        g_wcmb[n][k] = __float2half_rn(s * (1.0f / 3.0f));
    }
    if (i < GRIDB) g_state[i] = 0u;
    if (i < 64) {
        const float* b4 = bl + (size_t)3 * RR * HIDD;
        float s = 0.f;
        for (int j = 0; j < HIDD; j++) {
            float bj = (b4[j] + b4[HIDD + j] + b4[2 * HIDD + j]) * (1.0f / 3.0f);
            s = fmaf(bj, Wout[(size_t)j * 64 + i], s);
        }
        g_bcmb[i] = s + bout[i];
    }
}

__device__ __forceinline__ int warp_incl_scan(int v, int lane) {
    #pragma unroll
    for (int o = 1; o < 32; o <<= 1) {
        int t = __shfl_up_sync(0xFFFFFFFFu, v, o);
        if (lane >= o) v += t;
    }
    return v;
}

// ---------------- launch 1: norms + rowptr via decoupled lookback scan ----------------
__global__ __launch_bounds__(SB)
void scan_kernel() {
    int b = blockIdx.x;
    int r = b / NBLK, blk = b - r * NBLK;
    int tid = threadIdx.x, lane = tid & 31, wid = tid >> 5;
    __shared__ int ws[8];
    __shared__ int s_boff;

    int i = blk * SB + tid;
    int v = 0;
    if (i < NN) {
        int od = g_outdeg[r * NN + i];
        int id = g_indeg [r * NN + i];
        g_rout[r * NN + i] = rsqrtf(fmaxf((float)od, 1.0f));
        g_rin [r * NN + i] = rsqrtf(fmaxf((float)id, 1.0f));
        v = id;
    }
    // block sum
    int s = v;
    #pragma unroll
    for (int o = 16; o > 0; o >>= 1) s += __shfl_down_sync(0xFFFFFFFFu, s, o);
    if (lane == 0) ws[wid] = s;
    __syncthreads();
    if (tid == 0) {
        int bsum = 0;
        #pragma unroll
        for (int w = 0; w < 8; w++) bsum += ws[w];
        atomicExch(&g_state[b], (unsigned)bsum | FLAG_A);
        // lookback
        int run = 0;
        int lo = r * NBLK;
        for (int j = b - 1; j >= lo; j--) {
            unsigned st;
            do {
                st = *(volatile unsigned*)&g_state[j];
                if (!(st & (FLAG_A | FLAG_P))) __nanosleep(20);
            } while (!(st & (FLAG_A | FLAG_P)));
            run += (int)(st & VALMASK);
            if (st & FLAG_P) break;
        }
        atomicExch(&g_state[b], (unsigned)(run + bsum) | FLAG_P);
        s_boff = run;
    }
    __syncthreads();
    int boff = s_boff;

    // local exclusive scan
    int incl = warp_incl_scan(v, lane);
    if (lane == 31) ws[wid] = incl;
    __syncthreads();
    if (wid == 0) {
        int t = (lane < 8) ? ws[lane] : 0;
        t = warp_incl_scan(t, lane);
        if (lane < 8) ws[lane] = t;
    }
    __syncthreads();
    incl += (wid > 0) ? ws[wid - 1] : 0;
    int excl = boff + incl - v;
    if (i < NN) {
        g_rowptr[r * (NN + 1) + i] = excl;
        g_cursor[r * (NN + 1) + i] = excl;
    }
    if (blk == NBLK - 1 && tid == SB - 1)
        g_rowptr[r * (NN + 1) + NN] = boff + incl;
}

// ---------------- launch 2: fill edges (+ zero degree arrays for next replay) ----------------
__global__ void fill_kernel(const int* __restrict__ src, const int* __restrict__ dst) {
    int i = blockIdx.x * blockDim.x + threadIdx.x;
    if (i < RR * EE) {
        int r = i / EE;
        int d = dst[i];
        int s = src[i];
        int pos = atomicAdd(&g_cursor[r * (NN + 1) + d], 1);
        g_edge[(size_t)r * EE + pos] = make_int2(s, __float_as_int(g_rout[r * NN + s]));
    }
    if (i < RR * NN) { g_outdeg[i] = 0; g_indeg[i] = 0; }
}

// ---------------- SpMM: one warp per (relation, dst-row), MLP-8 fp16 gather ----------------
__global__ void spmm_kernel(int in_sel) {
    int gw   = (blockIdx.x * blockDim.x + threadIdx.x) >> 5;
    int lane = threadIdx.x & 31;
    if (gw >= RR * NN) return;
    int r = gw / NN;
    int n = gw - r * NN;

    const __half* hin = (in_sel < 0) ? g_xh : g_hh[in_sel];
    const uint2* h2 = (const uint2*)hin;
    const int2* edges = g_edge + (size_t)r * EE;

    int start = g_rowptr[r * (NN + 1) + n];
    int end   = g_rowptr[r * (NN + 1) + n + 1];

    float4 acc = make_float4(0.f, 0.f, 0.f, 0.f);
    int e = start;
    #pragma unroll 1
    for (; e + 8 <= end; e += 8) {
        int2 ed[8];
        #pragma unroll
        for (int j = 0; j < 8; j++) ed[j] = edges[e + j];
        uint2 u[8];
        #pragma unroll
        for (int j = 0; j < 8; j++) u[j] = h2[(size_t)ed[j].x * 32 + lane];
        #pragma unroll
        for (int j = 0; j < 8; j++) {
            float w = __int_as_float(ed[j].y);
            float2 a = __half22float2(*(__half2*)&u[j].x);
            float2 b = __half22float2(*(__half2*)&u[j].y);
            acc.x = fmaf(w, a.x, acc.x); acc.y = fmaf(w, a.y, acc.y);
            acc.z = fmaf(w, b.x, acc.z); acc.w = fmaf(w, b.y, acc.w);
        }
    }
    if (e + 4 <= end) {
        int2 ed[4];
        #pragma unroll
        for (int j = 0; j < 4; j++) ed[j] = edges[e + j];
        uint2 u[4];
        #pragma unroll
        for (int j = 0; j < 4; j++) u[j] = h2[(size_t)ed[j].x * 32 + lane];
        #pragma unroll
        for (int j = 0; j < 4; j++) {
            float w = __int_as_float(ed[j].y);
            float2 a = __half22float2(*(__half2*)&u[j].x);
            float2 b = __half22float2(*(__half2*)&u[j].y);
            acc.x = fmaf(w, a.x, acc.x); acc.y = fmaf(w, a.y, acc.y);
            acc.z = fmaf(w, b.x, acc.z); acc.w = fmaf(w, b.y, acc.w);
        }
        e += 4;
    }
    for (; e < end; e++) {
        int2 ed = edges[e];
        float w = __int_as_float(ed.y);
        uint2 u = h2[(size_t)ed.x * 32 + lane];
        float2 a = __half22float2(*(__half2*)&u.x), b = __half22float2(*(__half2*)&u.y);
        acc.x = fmaf(w, a.x, acc.x); acc.y = fmaf(w, a.y, acc.y);
        acc.z = fmaf(w, b.x, acc.z); acc.w = fmaf(w, b.y, acc.w);
    }
    float ri = g_rin[r * NN + n];
    uint2 o;
    *(__half2*)&o.x = __floats2half2_rn(acc.x * ri, acc.y * ri);
    *(__half2*)&o.y = __floats2half2_rn(acc.z * ri, acc.w * ri);
    ((uint2*)g_zh)[((size_t)n * RR + r) * 32 + lane] = o;
}

// ---------------- fp16 tensor-core GEMM: BM=64, warp tile 32x32, cp.async 2-stage ----------------
__device__ __forceinline__ void mma_f16(float* c, const uint32_t* a,
                                        uint32_t b0, uint32_t b1) {
    asm volatile(
        "mma.sync.aligned.m16n8k16.row.col.f32.f16.f16.f32 "
        "{%0,%1,%2,%3}, {%4,%5,%6,%7}, {%8,%9}, {%0,%1,%2,%3};"
        : "+f"(c[0]), "+f"(c[1]), "+f"(c[2]), "+f"(c[3])
        : "r"(a[0]), "r"(a[1]), "r"(a[2]), "r"(a[3]), "r"(b0), "r"(b1));
}

__device__ __forceinline__ void ldsm_x4(uint32_t* d, uint32_t addr) {
    asm volatile("ldmatrix.sync.aligned.m8n8.x4.shared.b16 {%0,%1,%2,%3}, [%4];"
                 : "=r"(d[0]), "=r"(d[1]), "=r"(d[2]), "=r"(d[3]) : "r"(addr));
}

__device__ __forceinline__ void cp_async16(void* smem_dst, const void* gsrc) {
    uint32_t d = (uint32_t)__cvta_generic_to_shared(smem_dst);
    asm volatile("cp.async.cg.shared.global [%0], [%1], 16;" :: "r"(d), "l"(gsrc));
}

// C[M,BN] = (A[M,K=384] @ Wt^T + bias) * alpha.
// wsel: 0..3 -> g_wt[wsel], 4 -> g_wcmb.  bias_sel: -1 -> g_bcmb else passed ptr.
// o_sel: 0/1 -> g_hh[o_sel] (fp16), 2 -> Cext (fp32).
template <int BN, int WN, int NT, int MINB>
__global__ __launch_bounds__(NT, MINB)
void gemm_tc_kernel(int wsel,
                    const float* __restrict__ bias, int biasRows, int bias_sel,
                    int o_sel, float* __restrict__ Cext,
                    float alpha, int leaky) {
    const int BM = 64, BK = 64, PAD = 8, LDW = BK + PAD;   // 72 halves
    const int K = KK, NK = K / BK;                          // 6
    const __half* A  = g_zh;
    const __half* Wt = (wsel < 4) ? &g_wt[wsel][0][0] : &g_wcmb[0][0];
    __half* Hout = (o_sel == 2) ? nullptr : g_hh[o_sel];
    const float* bptr = (bias_sel < 0) ? g_bcmb : bias;

    extern __shared__ __half smh[];
    __half* AsB = smh;                       // 2 stages of [BM][LDW]
    __half* BsB = smh + 2 * BM * LDW;        // 2 stages of [BN][LDW]

    int tid  = threadIdx.x;
    int wid  = tid >> 5;
    int lane = tid & 31;
    int g    = lane >> 2;
    int tg   = lane & 3;
    int wm   = wid / WN;                     // 0..1
    int wn   = wid % WN;                     // 0..WN-1
    int blockRow = blockIdx.x * BM;

    uint32_t as0 = (uint32_t)__cvta_generic_to_shared(AsB);
    uint32_t bs0 = (uint32_t)__cvta_generic_to_shared(BsB);

    // A ldmatrix lane addressing (m16 x k16 per x4)
    int a_row = wm * 32 + (lane & 15);       // + mt*16
    int a_col = (lane >> 4) * 8;             // + kb
    // B ldmatrix x4 lane addressing (two n8 tiles x k16 per x4)
    int bgrp  = lane >> 3;                   // 0..3
    int b_row = wn * 32 + (bgrp >> 1) * 8 + (lane & 7);   // + ntp*16
    int b_col = (bgrp & 1) * 8;              // + kb

    float acc[2][4][4];
    #pragma unroll
    for (int i = 0; i < 2; i++)
        #pragma unroll
        for (int j = 0; j < 4; j++)
            #pragma unroll
            for (int q = 0; q < 4; q++) acc[i][j][q] = 0.f;

    const int ASLOT = BM * (BK / 8);         // 512 uint4
    const int BSLOT = BN * (BK / 8);

    auto issue_load = [&](int st, int k0) {
        __half* As = AsB + st * BM * LDW;
        __half* Bs = BsB + st * BN * LDW;
        #pragma unroll
        for (int i = 0; i < ASLOT / NT; i++) {
            int v = tid + i * NT;
            int row = v >> 3, kq = v & 7;
            int gr = blockRow + row;
            void* dstp = &As[row * LDW + kq * 8];
            if (gr < NN) cp_async16(dstp, A + (size_t)gr * K + k0 + kq * 8);
            else         *(uint4*)dstp = make_uint4(0, 0, 0, 0);
        }
        #pragma unroll
        for (int i = 0; i < BSLOT / NT; i++) {
            int v = tid + i * NT;
            int n = v >> 3, kq = v & 7;
            cp_async16(&Bs[n * LDW + kq * 8], Wt + (size_t)n * K + k0 + kq * 8);
        }
    };

    issue_load(0, 0);
    asm volatile("cp.async.commit_group;");

    for (int kt = 0; kt < NK; kt++) {
        if (kt + 1 < NK) {
            issue_load((kt + 1) & 1, (kt + 1) * BK);
            asm volatile("cp.async.commit_group;");
            asm volatile("cp.async.wait_group 1;");
        } else {
            asm volatile("cp.async.wait_group 0;");
        }
        __syncthreads();

        int st = kt & 1;
        uint32_t as_base = as0 + (uint32_t)(st * BM * LDW * 2);
        uint32_t bs_base = bs0 + (uint32_t)(st * BN * LDW * 2);

        #pragma unroll
        for (int kk = 0; kk < BK / 16; kk++) {
            int kb = kk * 16;
            uint32_t af[2][4];
            #pragma unroll
            for (int mt = 0; mt < 2; mt++) {
                uint32_t addr = as_base +
                    (uint32_t)(((a_row + mt * 16) * LDW + kb + a_col) * 2);
                ldsm_x4(af[mt], addr);
            }
            uint32_t bf[2][4];
            #pragma unroll
            for (int ntp = 0; ntp < 2; ntp++) {
                uint32_t addr = bs_base +
                    (uint32_t)(((b_row + ntp * 16) * LDW + kb + b_col) * 2);
                ldsm_x4(bf[ntp], addr);
            }
            #pragma unroll
            for (int mt = 0; mt < 2; mt++)
                #pragma unroll
                for (int ntp = 0; ntp < 2; ntp++) {
                    mma_f16(acc[mt][ntp * 2],     af[mt], bf[ntp][0], bf[ntp][1]);
                    mma_f16(acc[mt][ntp * 2 + 1], af[mt], bf[ntp][2], bf[ntp][3]);
                }
        }
        __syncthreads();
    }

    // ---- epilogue ----
    float2 bs[4];
    #pragma unroll
    for (int nt = 0; nt < 4; nt++) {
        int col = wn * 32 + nt * 8 + tg * 2;
        float sx = 0.f, sy = 0.f;
        for (int rr = 0; rr < biasRows; rr++) {
            sx += bptr[rr * BN + col];
            sy += bptr[rr * BN + col + 1];
        }
        bs[nt].x = sx; bs[nt].y = sy;
    }
    #pragma unroll
    for (int mt = 0; mt < 2; mt++) {
        int r0 = blockRow + wm * 32 + mt * 16 + g;
        int r1 = r0 + 8;
        #pragma unroll
        for (int nt = 0; nt < 4; nt++) {
            int col = wn * 32 + nt * 8 + tg * 2;
            float v0 = (acc[mt][nt][0] + bs[nt].x) * alpha;
            float v1 = (acc[mt][nt][1] + bs[nt].y) * alpha;
            float v2 = (acc[mt][nt][2] + bs[nt].x) * alpha;
            float v3 = (acc[mt][nt][3] + bs[nt].y) * alpha;
            if (leaky) {
                if (v0 < 0.f) v0 *= 0.01f;
                if (v1 < 0.f) v1 *= 0.01f;
                if (v2 < 0.f) v2 *= 0.01f;
                if (v3 < 0.f) v3 *= 0.01f;
            }
            if (o_sel == 2) {
                if (r0 < NN) *(float2*)(Cext + (size_t)r0 * BN + col) = make_float2(v0, v1);
                if (r1 < NN) *(float2*)(Cext + (size_t)r1 * BN + col) = make_float2(v2, v3);
            } else {
                if (r0 < NN) *(__half2*)(Hout + (size_t)r0 * HIDD + col) = __floats2half2_rn(v0, v1);
                if (r1 < NN) *(__half2*)(Hout + (size_t)r1 * HIDD + col) = __floats2half2_rn(v2, v3);
            }
        }
    }
}

// ---------------- launcher ----------------
extern "C" void kernel_launch(void* const* d_in, const int* in_sizes, int n_in,
                              void* d_out, int out_size) {
    const float* x    = (const float*)d_in[0];
    const int*   esrc = (const int*)  d_in[1];
    const int*   edst = (const int*)  d_in[2];
    const float* W0   = (const float*)d_in[3];
    const float* b0   = (const float*)d_in[4];
    const float* Wl   = (const float*)d_in[5];
    const float* bl   = (const float*)d_in[6];
    const float* Wout = (const float*)d_in[7];
    const float* bout = (const float*)d_in[8];
    float* out = (float*)d_out;

    const int SM128 = 2 * (64 + 128) * 72 * 2;   // 55296 B
    const int SM64  = 2 * (64 + 64)  * 72 * 2;   // 36864 B
    cudaFuncSetAttribute((const void*)gemm_tc_kernel<128, 4, 256, 3>,
                         cudaFuncAttributeMaxDynamicSharedMemorySize, SM128);
    cudaFuncSetAttribute((const void*)gemm_tc_kernel<64, 2, 128, 4>,
                         cudaFuncAttributeMaxDynamicSharedMemorySize, SM64);

    // launches 0-2: preproc; launch 3: spmm (ncu window target)
    predeg_kernel<<<(NN * HIDD / 2 + 255) / 256, 256>>>(x, esrc, edst, W0, Wl, bl, Wout, bout);
    scan_kernel<<<GRIDB, SB>>>();
    fill_kernel<<<(RR * EE + 255) / 256, 256>>>(esrc, edst);

    const int spmm_blocks = (RR * NN * 32 + 255) / 256;
    const int gemm_blocks = (NN + 63) / 64;   // 782
    const float inv_r = 1.0f / (float)RR;

    spmm_kernel<<<spmm_blocks, 256>>>(-1);
    gemm_tc_kernel<128, 4, 256, 3><<<gemm_blocks, 256, SM128>>>(
        0, b0, RR, 0, 0, nullptr, inv_r, 1);
    for (int l = 0; l < 3; l++) {
        spmm_kernel<<<spmm_blocks, 256>>>(l & 1 ? 1 : 0);
        gemm_tc_kernel<128, 4, 256, 3><<<gemm_blocks, 256, SM128>>>(
            l + 1, bl + (size_t)l * RR * HIDD, RR, 0,
            (l & 1) ? 0 : 1, nullptr, inv_r, 1);
    }
    // conv layer 4 + final linear folded
    spmm_kernel<<<spmm_blocks, 256>>>(1);
    gemm_tc_kernel<64, 2, 128, 4><<<gemm_blocks, 128, SM64>>>(
        4, nullptr, 1, -1, 2, out, 1.0f, 0);
}